// round 14
// baseline (speedup 1.0000x reference)
#include <cuda_runtime.h>
#include <cuda_fp16.h>
#include <cstdint>

#define BB   2
#define SQ   2048
#define DD   1024
#define NH   16
#define HD   64
#define BH   (BB*NH)      // 32
#define NREL 129
#define QRS  136          // qrel row stride (padded so mma tile 16 fits)

// ---------------- scratch (device globals: sanctioned workaround) ----------
__device__ __half g_xh[(size_t)BB * SQ * DD];    // X fp16, k pair-permuted
__device__ __half g_wth[3 * (size_t)DD * DD];    // W^T [n][k] fp16, k pair-permuted
__device__ __half g_qh[(size_t)BH * SQ * HD];    // [bh][s][d]  fp16, natural cols
__device__ __half g_kh[(size_t)BH * SQ * HD];    // [bh][s][d]  fp16, pair-permuted d
__device__ __half g_vth[(size_t)BH * HD * SQ];   // [bh][d][s]  fp16, pair-permuted s
__device__ float  g_qrel[(size_t)BH * SQ * QRS]; // [bh][q][129 (pad 136)] fp32

// ---------------- helpers --------------------------------------------------
__device__ __forceinline__ float ex2f(float x) {
    float r; asm("ex2.approx.f32 %0, %1;" : "=f"(r) : "f"(x));
    return r;
}
__device__ __forceinline__ uint32_t h2b(float lo, float hi) {
    __half2 h = __floats2half2_rn(lo, hi);
    return *(uint32_t*)&h;
}
// pair-interleave permutation within 16-element blocks:
// pair j (j<4) -> slot 2j ; pair j (j>=4) -> slot 2(j-4)+1
__device__ __forceinline__ int sperm(int s) {
    int j = (s >> 1) & 7;
    return (s & ~15) + ((((j & 3) << 1) | (j >> 2)) << 1) + (s & 1);
}
__device__ __forceinline__ int pslot(int j) {   // pair j -> pair-slot
    return (j < 4) ? 2 * j : 2 * j - 7;
}
// fp16 k16 mma
__device__ __forceinline__ void mma16(float4& d,
                                      uint32_t a0, uint32_t a1, uint32_t a2, uint32_t a3,
                                      uint32_t b0, uint32_t b1) {
    asm("mma.sync.aligned.m16n8k16.row.col.f32.f16.f16.f32 "
        "{%0,%1,%2,%3},{%4,%5,%6,%7},{%8,%9},{%0,%1,%2,%3};"
        : "+f"(d.x), "+f"(d.y), "+f"(d.z), "+f"(d.w)
        : "r"(a0), "r"(a1), "r"(a2), "r"(a3), "r"(b0), "r"(b1));
}

// ===========================================================================
// Kernel 0a: X -> fp16, k pair-permuted per 16-block. One 16-block/thread.
// ===========================================================================
__global__ __launch_bounds__(256) void convert_x(const float* __restrict__ X)
{
    const int idx = blockIdx.x * 256 + threadIdx.x;      // 16-block index
    const float4* src = (const float4*)X + (size_t)idx * 4;
    __half* dst = g_xh + (size_t)idx * 16;
    float f[16];
    *(float4*)(f)      = src[0];
    *(float4*)(f + 4)  = src[1];
    *(float4*)(f + 8)  = src[2];
    *(float4*)(f + 12) = src[3];
    #pragma unroll
    for (int j = 0; j < 8; j++)
        *(__half2*)&dst[2 * pslot(j)] = __floats2half2_rn(f[2 * j], f[2 * j + 1]);
}

// ===========================================================================
// Kernel 0b: W[k][n] -> W^T[n][k] fp16, k pair-permuted. 32x32 smem transpose.
// ===========================================================================
__global__ __launch_bounds__(256) void convert_w(
    const float* __restrict__ Wq, const float* __restrict__ Wk,
    const float* __restrict__ Wv)
{
    __shared__ float tile[32][33];
    const float* W = (blockIdx.z == 0) ? Wq : (blockIdx.z == 1) ? Wk : Wv;
    __half* out = g_wth + (size_t)blockIdx.z * DD * DD;
    const int k0 = blockIdx.y * 32, n0 = blockIdx.x * 32;
    const int t = threadIdx.x;
    {
        const int r = t >> 3, c = (t & 7) * 4;
        float4 v = *(const float4*)&W[(size_t)(k0 + r) * DD + n0 + c];
        tile[r][c] = v.x; tile[r][c + 1] = v.y; tile[r][c + 2] = v.z; tile[r][c + 3] = v.w;
    }
    __syncthreads();
    if (t < 64) {
        const int n = t >> 1, blk = t & 1;
        __half* drow = out + (size_t)(n0 + n) * DD + k0 + blk * 16;
        #pragma unroll
        for (int j = 0; j < 8; j++)
            *(__half2*)&drow[2 * pslot(j)] =
                __floats2half2_rn(tile[blk * 16 + 2 * j][n], tile[blk * 16 + 2 * j + 1][n]);
    }
}

// ===========================================================================
// Kernel 1: fused QKV projection, fp16 m16n8k16, pre-converted inputs.
// (unchanged from R10/R11 — measured good)
// ===========================================================================
#define AST 48   // smem row stride (halves)

__global__ __launch_bounds__(256) void qkv_gemm(
    const float* __restrict__ bq, const float* __restrict__ bk,
    const float* __restrict__ bv)
{
    __shared__ __half As[2][128 * AST];
    __shared__ __half Bs[2][128 * AST];

    const float* bias = (blockIdx.z == 0) ? bq : (blockIdx.z == 1) ? bk : bv;
    const __half* Wt = g_wth + (size_t)blockIdx.z * DD * DD;

    const int tid = threadIdx.x;
    const int wid = tid >> 5, lane = tid & 31, lr = lane >> 2, lc = lane & 3;
    const int wm = wid >> 1, wn = wid & 1;
    const int m0 = blockIdx.y * 128, n0 = blockIdx.x * 128;

    const int row = tid >> 1, hb = tid & 1;
    const __half* xp = g_xh + (size_t)(m0 + row) * DD + hb * 16;
    const __half* wp = Wt   + (size_t)(n0 + row) * DD + hb * 16;

    float4 acc[2][8];
    #pragma unroll
    for (int mt = 0; mt < 2; mt++)
        #pragma unroll
        for (int nt = 0; nt < 8; nt++) acc[mt][nt] = make_float4(0.f, 0.f, 0.f, 0.f);

    uint4 xa0 = *(const uint4*)(xp);
    uint4 xa1 = *(const uint4*)(xp + 8);
    uint4 wa0 = *(const uint4*)(wp);
    uint4 wa1 = *(const uint4*)(wp + 8);

    *(uint4*)&As[0][row * AST + hb * 24]     = xa0;
    *(uint4*)&As[0][row * AST + hb * 24 + 8] = xa1;
    *(uint4*)&Bs[0][row * AST + hb * 24]     = wa0;
    *(uint4*)&Bs[0][row * AST + hb * 24 + 8] = wa1;
    __syncthreads();

    for (int k0 = 0; k0 < DD; k0 += 32) {
        const int cur = (k0 >> 5) & 1;
        const bool haveNext = (k0 + 32) < DD;
        if (haveNext) {
            xa0 = *(const uint4*)(xp + k0 + 32);
            xa1 = *(const uint4*)(xp + k0 + 40);
            wa0 = *(const uint4*)(wp + k0 + 32);
            wa1 = *(const uint4*)(wp + k0 + 40);
        }

        const __half* Ac = As[cur];
        const __half* Bc = Bs[cur];
        #pragma unroll
        for (int kc = 0; kc < 2; kc++) {
            uint2 ua[2], ub[2];
            #pragma unroll
            for (int mt = 0; mt < 2; mt++) {
                const int mb = wm * 32 + mt * 16;
                ua[mt] = *(const uint2*)&Ac[(mb + lr) * AST + kc * 24 + 4 * lc];
                ub[mt] = *(const uint2*)&Ac[(mb + lr + 8) * AST + kc * 24 + 4 * lc];
            }
            #pragma unroll
            for (int nt = 0; nt < 8; nt++) {
                const int nb = wn * 64 + nt * 8;
                const uint2 vb = *(const uint2*)&Bc[(nb + lr) * AST + kc * 24 + 4 * lc];
                mma16(acc[0][nt], ua[0].x, ub[0].x, ua[0].y, ub[0].y, vb.x, vb.y);
                mma16(acc[1][nt], ua[1].x, ub[1].x, ua[1].y, ub[1].y, vb.x, vb.y);
            }
        }

        if (haveNext) {
            __half* Ab = As[cur ^ 1];
            __half* Bb = Bs[cur ^ 1];
            *(uint4*)&Ab[row * AST + hb * 24]     = xa0;
            *(uint4*)&Ab[row * AST + hb * 24 + 8] = xa1;
            *(uint4*)&Bb[row * AST + hb * 24]     = wa0;
            *(uint4*)&Bb[row * AST + hb * 24 + 8] = wa1;
        }
        __syncthreads();
    }

    // ---- epilogue: add bias, fp16 scatter ----
    if (blockIdx.z == 0) {
        #pragma unroll
        for (int mt = 0; mt < 2; mt++) {
            const int mA = m0 + wm * 32 + mt * 16 + lr;
            const int mB = mA + 8;
            #pragma unroll
            for (int nt = 0; nt < 8; nt++) {
                const int n = n0 + wn * 64 + nt * 8 + 2 * lc;
                const float b0v = __ldg(&bias[n]), b1v = __ldg(&bias[n + 1]);
                const int hh = n >> 6, dd = n & 63;
                {
                    const int bidx = mA >> 11, s = mA & 2047;
                    *(__half2*)&g_qh[(((size_t)(bidx * NH + hh)) * SQ + s) * HD + dd] =
                        __floats2half2_rn(acc[mt][nt].x + b0v, acc[mt][nt].y + b1v);
                }
                {
                    const int bidx = mB >> 11, s = mB & 2047;
                    *(__half2*)&g_qh[(((size_t)(bidx * NH + hh)) * SQ + s) * HD + dd] =
                        __floats2half2_rn(acc[mt][nt].z + b0v, acc[mt][nt].w + b1v);
                }
            }
        }
    } else if (blockIdx.z == 1) {
        #pragma unroll
        for (int mt = 0; mt < 2; mt++) {
            const int mA = m0 + wm * 32 + mt * 16 + lr;
            const int mB = mA + 8;
            #pragma unroll
            for (int nt = 0; nt < 8; nt++) {
                const int n = n0 + wn * 64 + nt * 8 + 2 * lc;
                const float b0v = __ldg(&bias[n]), b1v = __ldg(&bias[n + 1]);
                const int hh = n >> 6, dd = n & 63;
                const int pc = sperm(dd);
                {
                    const int bidx = mA >> 11, s = mA & 2047;
                    *(__half2*)&g_kh[(((size_t)(bidx * NH + hh)) * SQ + s) * HD + pc] =
                        __floats2half2_rn(acc[mt][nt].x + b0v, acc[mt][nt].y + b1v);
                }
                {
                    const int bidx = mB >> 11, s = mB & 2047;
                    *(__half2*)&g_kh[(((size_t)(bidx * NH + hh)) * SQ + s) * HD + pc] =
                        __floats2half2_rn(acc[mt][nt].z + b0v, acc[mt][nt].w + b1v);
                }
            }
        }
    } else {
        #pragma unroll
        for (int mt = 0; mt < 2; mt++) {
            const int mA = m0 + wm * 32 + mt * 16 + lr;
            const int mB = mA + 8;
            const int bA = mA >> 11, sA = mA & 2047;
            const int bB = mB >> 11, sB = mB & 2047;
            const int pA = sperm(sA), pB = sperm(sB);
            #pragma unroll
            for (int nt = 0; nt < 8; nt++) {
                const int n = n0 + wn * 64 + nt * 8 + 2 * lc;
                const float b0v = __ldg(&bias[n]), b1v = __ldg(&bias[n + 1]);
                const int hh = n >> 6, dd = n & 63;
                const size_t base0 = ((size_t)(bA * NH + hh) * HD + dd) * SQ;
                const size_t base1 = ((size_t)(bB * NH + hh) * HD + dd) * SQ;
                g_vth[base0 + pA]      = __float2half_rn(acc[mt][nt].x + b0v);
                g_vth[base0 + SQ + pA] = __float2half_rn(acc[mt][nt].y + b1v);
                g_vth[base1 + pB]      = __float2half_rn(acc[mt][nt].z + b0v);
                g_vth[base1 + SQ + pB] = __float2half_rn(acc[mt][nt].w + b1v);
            }
        }
    }
}

// ===========================================================================
// Kernel 2: qrel via fp16 mma (unchanged from R11 — 22us measured)
// ===========================================================================
__global__ __launch_bounds__(256) void qrel_mma(const float* __restrict__ emb_k)
{
    __shared__ __half ekh[136 * 80];
    const int tid = threadIdx.x;
    const int wid = tid >> 5, lane = tid & 31, lr = lane >> 2, lc = lane & 3;
    const int bh = blockIdx.y, q0 = blockIdx.x * 128;
    const int r0w = wid * 16;
    const int rowA = r0w + lr, rowB = rowA + 8;

    for (int idx = tid; idx < 136 * 32; idx += 256) {
        const int r = idx >> 5, j = idx & 31;
        const int blk = j >> 3, jj = j & 7;
        float lo = 0.f, hi = 0.f;
        if (r < NREL) {
            lo = emb_k[r * HD + blk * 16 + 2 * jj];
            hi = emb_k[r * HD + blk * 16 + 2 * jj + 1];
        }
        *(__half2*)&ekh[r * 80 + blk * 16 + 2 * pslot(jj)] = __floats2half2_rn(lo, hi);
    }

    uint32_t qf[4][4];
    {
        const __half* qA = g_qh + ((size_t)bh * SQ + q0 + rowA) * HD;
        const __half* qB = qA + 8 * HD;
        #pragma unroll
        for (int kc = 0; kc < 4; kc++) {
            qf[kc][0] = *(const uint32_t*)&qA[kc * 16 + 2 * lc];
            qf[kc][1] = *(const uint32_t*)&qB[kc * 16 + 2 * lc];
            qf[kc][2] = *(const uint32_t*)&qA[kc * 16 + 2 * lc + 8];
            qf[kc][3] = *(const uint32_t*)&qB[kc * 16 + 2 * lc + 8];
        }
    }
    __syncthreads();

    float4 racc[17];
    #pragma unroll
    for (int nt = 0; nt < 17; nt++) racc[nt] = make_float4(0.f, 0.f, 0.f, 0.f);
    const uint2* E2 = (const uint2*)ekh;
    #pragma unroll
    for (int kc = 0; kc < 4; kc++) {
        #pragma unroll
        for (int nt = 0; nt < 17; nt++) {
            const uint2 eb = E2[(nt * 8 + lr) * 20 + kc * 4 + lc];
            mma16(racc[nt], qf[kc][0], qf[kc][1], qf[kc][2], qf[kc][3], eb.x, eb.y);
        }
    }

    float* orA = g_qrel + ((size_t)bh * SQ + q0 + rowA) * QRS;
    float* orB = g_qrel + ((size_t)bh * SQ + q0 + rowB) * QRS;
    #pragma unroll
    for (int nt = 0; nt < 17; nt++) {
        const int c0 = nt * 8 + 2 * lc;
        *(float2*)&orA[c0] = make_float2(racc[nt].x, racc[nt].y);
        *(float2*)&orB[c0] = make_float2(racc[nt].z, racc[nt].w);
    }
}

// ===========================================================================
// Kernel 3: flash attention, fp16 m16n8k16. fp32 pw / 2 CTAs (374us config);
// single new change: K/V/mask tile prefetch into registers so per-tile LDG
// latency overlaps the previous tile's compute.
// ===========================================================================
#define PWS 144
#define ATTN_SMEM_BYTES (10240 + 10240 + 128 * PWS * 4 + 256)
#define C1LOG2E 0.18033688011112042f    // 0.125 * log2(e)
#define LOG2E   1.4426950408889634f

__global__ __launch_bounds__(256, 2) void attn_f16(
    const float* __restrict__ mask,
    const float* __restrict__ emb_v,
    float* __restrict__ out)
{
    extern __shared__ char smc[];
    __half* Ks = (__half*)smc;                       // [64][80]
    __half* Vt = (__half*)(smc + 10240);             // [64(d)][80(s)]
    float*  pw = (float*)(smc + 20480);              // [128][144]
    float* msk = (float*)(smc + 20480 + 128 * PWS * 4);

    const int tid = threadIdx.x;
    const int wid = tid >> 5, lane = tid & 31, lr = lane >> 2, lc = lane & 3;
    const int bh = blockIdx.y, b = bh >> 4, h = bh & 15;
    const int q0 = blockIdx.x * 128;
    const int r0w = wid * 16;
    const int rowA = r0w + lr, rowB = rowA + 8;

    for (int i = lane; i < 16 * PWS; i += 32) pw[r0w * PWS + i] = 0.f;

    uint32_t qf[4][4];
    {
        const __half* qA = g_qh + ((size_t)bh * SQ + q0 + rowA) * HD;
        const __half* qB = qA + 8 * HD;
        #pragma unroll
        for (int kc = 0; kc < 4; kc++) {
            qf[kc][0] = *(const uint32_t*)&qA[kc * 16 + 2 * lc];
            qf[kc][1] = *(const uint32_t*)&qB[kc * 16 + 2 * lc];
            qf[kc][2] = *(const uint32_t*)&qA[kc * 16 + 2 * lc + 8];
            qf[kc][3] = *(const uint32_t*)&qB[kc * 16 + 2 * lc + 8];
        }
    }
    const float* qrA = g_qrel + ((size_t)bh * SQ + q0 + rowA) * QRS;
    const float* qrB = g_qrel + ((size_t)bh * SQ + q0 + rowB) * QRS;
    const float rb0A = qrA[0], rb1A = qrA[128];
    const float rb0B = qrB[0], rb1B = qrB[128];

    float l_a = 0.f, l_b = 0.f;
    float h0A = 0.f, h1A = 0.f, h0B = 0.f, h1B = 0.f;
    float4 acc[8];
    #pragma unroll
    for (int nt = 0; nt < 8; nt++) acc[nt] = make_float4(0.f, 0.f, 0.f, 0.f);

    // loader geometry + tile-0 prefetch into registers
    const int frow = tid >> 2, fcq = (tid & 3) * 16;
    const __half* kbase = g_kh  + ((size_t)bh * SQ + frow) * HD + fcq;   // +k0*HD
    const __half* vbase = g_vth + ((size_t)bh * HD + frow) * SQ + fcq;   // +k0
    uint4 pk0 = *(const uint4*)(kbase);
    uint4 pk1 = *(const uint4*)(kbase + 8);
    uint4 pv0 = *(const uint4*)(vbase);
    uint4 pv1 = *(const uint4*)(vbase + 8);
    float pmsk = (tid < 64) ? mask[(size_t)b * SQ + tid] : 0.f;

    for (int k0 = 0; k0 < SQ; k0 += 64) {
        __syncthreads();   // previous tile fully consumed
        // store prefetched tile
        *(uint4*)&Ks[frow * 80 + fcq]     = pk0;
        *(uint4*)&Ks[frow * 80 + fcq + 8] = pk1;
        *(uint4*)&Vt[frow * 80 + fcq]     = pv0;
        *(uint4*)&Vt[frow * 80 + fcq + 8] = pv1;
        if (tid < 64) msk[tid] = pmsk * LOG2E;
        __syncthreads();

        // prefetch next tile while computing this one
        if (k0 + 64 < SQ) {
            const __half* kp = kbase + (size_t)(k0 + 64) * HD;
            const __half* vp = vbase + (k0 + 64);
            pk0 = *(const uint4*)(kp);
            pk1 = *(const uint4*)(kp + 8);
            pv0 = *(const uint4*)(vp);
            pv1 = *(const uint4*)(vp + 8);
            if (tid < 64) pmsk = mask[(size_t)b * SQ + k0 + 64 + tid];
        }

        const int diff = q0 - k0;
        const bool nearT = (diff >= -128) && (diff <= 64);
        const int delta = diff + 64;

        float4 sc4[8];
        #pragma unroll
        for (int nt = 0; nt < 8; nt++) sc4[nt] = make_float4(0.f, 0.f, 0.f, 0.f);
        {
            const uint2* K2 = (const uint2*)Ks;
            #pragma unroll
            for (int kc = 0; kc < 4; kc++) {
                #pragma unroll
                for (int nt = 0; nt < 8; nt++) {
                    const uint2 kb = K2[(nt * 8 + lr) * 20 + kc * 4 + lc];
                    mma16(sc4[nt], qf[kc][0], qf[kc][1], qf[kc][2], qf[kc][3], kb.x, kb.y);
                }
            }
        }

        if (nearT) {
            #pragma unroll
            for (int nt = 0; nt < 8; nt++) {
                const int c0 = nt * 8 + 2 * lc;
                const float2 mk = *(const float2*)&msk[c0];
                const int bA = rowA + delta - c0;
                const int bB = rowB + delta - c0;
                const int bAx = min(max(bA, 0), 128),     bAy = min(max(bA - 1, 0), 128);
                const int bBx = min(max(bB, 0), 128),     bBy = min(max(bB - 1, 0), 128);
                sc4[nt].x = (sc4[nt].x + __ldg(&qrA[bAx])) * C1LOG2E + mk.x;
                sc4[nt].y = (sc4[nt].y + __ldg(&qrA[bAy])) * C1LOG2E + mk.y;
                sc4[nt].z = (sc4[nt].z + __ldg(&qrB[bBx])) * C1LOG2E + mk.x;
                sc4[nt].w = (sc4[nt].w + __ldg(&qrB[bBy])) * C1LOG2E + mk.y;
            }
        } else {
            const float rbA = (diff > 0) ? rb1A : rb0A;
            const float rbB = (diff > 0) ? rb1B : rb0B;
            #pragma unroll
            for (int nt = 0; nt < 8; nt++) {
                const int c0 = nt * 8 + 2 * lc;
                const float2 mk = *(const float2*)&msk[c0];
                sc4[nt].x = (sc4[nt].x + rbA) * C1LOG2E + mk.x;
                sc4[nt].y = (sc4[nt].y + rbA) * C1LOG2E + mk.y;
                sc4[nt].z = (sc4[nt].z + rbB) * C1LOG2E + mk.x;
                sc4[nt].w = (sc4[nt].w + rbB) * C1LOG2E + mk.y;
            }
        }

        float psA = 0.f, psB = 0.f;
        #pragma unroll
        for (int nt = 0; nt < 8; nt++) {
            sc4[nt].x = ex2f(sc4[nt].x); psA += sc4[nt].x;
            sc4[nt].y = ex2f(sc4[nt].y); psA += sc4[nt].y;
            sc4[nt].z = ex2f(sc4[nt].z); psB += sc4[nt].z;
            sc4[nt].w = ex2f(sc4[nt].w); psB += sc4[nt].w;
        }

        if (!nearT) {
            if (diff > 0) { h1A += psA; h1B += psB; }
            else          { h0A += psA; h0B += psB; }
        } else {
            #pragma unroll
            for (int nt = 0; nt < 8; nt++) {
                const int c0 = nt * 8 + 2 * lc;
                const int bA = rowA + delta - c0;
                const int bB = rowB + delta - c0;
                if (bA >= 128) h1A += sc4[nt].x; else if (bA <= 0) h0A += sc4[nt].x; else pw[rowA * PWS + bA] += sc4[nt].x;
                if (bA - 1 >= 128) h1A += sc4[nt].y; else if (bA - 1 <= 0) h0A += sc4[nt].y; else pw[rowA * PWS + bA - 1] += sc4[nt].y;
                if (bB >= 128) h1B += sc4[nt].z; else if (bB <= 0) h0B += sc4[nt].z; else pw[rowB * PWS + bB] += sc4[nt].z;
                if (bB - 1 >= 128) h1B += sc4[nt].w; else if (bB - 1 <= 0) h0B += sc4[nt].w; else pw[rowB * PWS + bB - 1] += sc4[nt].w;
            }
        }

        psA += __shfl_xor_sync(0xffffffffu, psA, 1);
        psA += __shfl_xor_sync(0xffffffffu, psA, 2);
        psB += __shfl_xor_sync(0xffffffffu, psB, 1);
        psB += __shfl_xor_sync(0xffffffffu, psB, 2);
        l_a += psA; l_b += psB;

        {
            const uint2* V2 = (const uint2*)Vt;
            #pragma unroll
            for (int kc = 0; kc < 4; kc++) {
                const uint32_t a0 = h2b(sc4[2 * kc].x,     sc4[2 * kc].y);
                const uint32_t a1 = h2b(sc4[2 * kc].z,     sc4[2 * kc].w);
                const uint32_t a2 = h2b(sc4[2 * kc + 1].x, sc4[2 * kc + 1].y);
                const uint32_t a3 = h2b(sc4[2 * kc + 1].z, sc4[2 * kc + 1].w);
                #pragma unroll
                for (int nt = 0; nt < 8; nt++) {
                    const uint2 vb = V2[(nt * 8 + lr) * 20 + kc * 4 + lc];
                    mma16(acc[nt], a0, a1, a2, a3, vb.x, vb.y);
                }
            }
        }
    }

    h0A += __shfl_xor_sync(0xffffffffu, h0A, 1);
    h0A += __shfl_xor_sync(0xffffffffu, h0A, 2);
    h1A += __shfl_xor_sync(0xffffffffu, h1A, 1);
    h1A += __shfl_xor_sync(0xffffffffu, h1A, 2);
    h0B += __shfl_xor_sync(0xffffffffu, h0B, 1);
    h0B += __shfl_xor_sync(0xffffffffu, h0B, 2);
    h1B += __shfl_xor_sync(0xffffffffu, h1B, 1);
    h1B += __shfl_xor_sync(0xffffffffu, h1B, 2);
    if (lc == 0) {
        pw[rowA * PWS + 0]   += h0A;
        pw[rowA * PWS + 128] += h1A;
        pw[rowB * PWS + 0]   += h0B;
        pw[rowB * PWS + 128] += h1B;
    }
    __syncthreads();

    __half* evt = (__half*)smc;   // 64*144*2 = 18432B <= 20480B
    for (int idx = tid; idx < 64 * PWS; idx += 256) {
        const int d = idx / PWS, r = idx - d * PWS;
        evt[idx] = (r < NREL) ? __float2half_rn(emb_v[r * HD + d]) : __half(0.f);
    }
    __syncthreads();

    float4 racc[8];
    #pragma unroll
    for (int nt = 0; nt < 8; nt++) racc[nt] = make_float4(0.f, 0.f, 0.f, 0.f);
    #pragma unroll
    for (int kc = 0; kc < 9; kc++) {   // k = 144 = 9 * 16
        const int kb = kc * 16 + 2 * lc;
        const uint32_t a0 = h2b(pw[rowA * PWS + kb],     pw[rowA * PWS + kb + 1]);
        const uint32_t a1 = h2b(pw[rowB * PWS + kb],     pw[rowB * PWS + kb + 1]);
        const uint32_t a2 = h2b(pw[rowA * PWS + kb + 8], pw[rowA * PWS + kb + 9]);
        const uint32_t a3 = h2b(pw[rowB * PWS + kb + 8], pw[rowB * PWS + kb + 9]);
        #pragma unroll
        for (int nt = 0; nt < 8; nt++) {
            const uint32_t b0 = *(const uint32_t*)&evt[(nt * 8 + lr) * PWS + kb];
            const uint32_t b1 = *(const uint32_t*)&evt[(nt * 8 + lr) * PWS + kb + 8];
            mma16(racc[nt], a0, a1, a2, a3, b0, b1);
        }
    }

    const float rlA = 1.f / l_a, rlB = 1.f / l_b;
    float* opA = out + ((size_t)(b * SQ + q0 + rowA)) * DD + h * HD;
    float* opB = out + ((size_t)(b * SQ + q0 + rowB)) * DD + h * HD;
    #pragma unroll
    for (int nt = 0; nt < 8; nt++) {
        const int c0 = nt * 8 + 2 * lc;
        float2 oa;
        oa.x = (acc[nt].x + racc[nt].x) * rlA;
        oa.y = (acc[nt].y + racc[nt].y) * rlA;
        *(float2*)&opA[c0] = oa;
        float2 ob;
        ob.x = (acc[nt].z + racc[nt].z) * rlB;
        ob.y = (acc[nt].w + racc[nt].w) * rlB;
        *(float2*)&opB[c0] = ob;
    }
}

// ===========================================================================
extern "C" void kernel_launch(void* const* d_in, const int* in_sizes, int n_in,
                              void* d_out, int out_size)
{
    const float* hidden = (const float*)d_in[0];
    const float* mask   = (const float*)d_in[1];
    const float* Wq     = (const float*)d_in[2];
    const float* bq     = (const float*)d_in[3];
    const float* Wk     = (const float*)d_in[4];
    const float* bk     = (const float*)d_in[5];
    const float* Wv     = (const float*)d_in[6];
    const float* bv     = (const float*)d_in[7];
    const float* emb_k  = (const float*)d_in[8];
    const float* emb_v  = (const float*)d_in[9];
    float* out = (float*)d_out;

    convert_x<<<(BB * SQ * DD / 16) / 256, 256>>>(hidden);
    dim3 gw(DD / 32, DD / 32, 3);
    convert_w<<<gw, 256>>>(Wq, Wk, Wv);

    dim3 g1(DD / 128, (BB * SQ) / 128, 3);
    qkv_gemm<<<g1, 256>>>(bq, bk, bv);

    dim3 g2(SQ / 128, BH);
    qrel_mma<<<g2, 256>>>(emb_k);

    cudaFuncSetAttribute(attn_f16, cudaFuncAttributeMaxDynamicSharedMemorySize,
                         ATTN_SMEM_BYTES);
    dim3 g3(SQ / 128, BH);
    attn_f16<<<g3, 256, ATTN_SMEM_BYTES>>>(mask, emb_v, out);
}

// round 15
// speedup vs baseline: 1.0577x; 1.0577x over previous
#include <cuda_runtime.h>
#include <cuda_fp16.h>
#include <cstdint>

#define BB   2
#define SQ   2048
#define DD   1024
#define NH   16
#define HD   64
#define BH   (BB*NH)      // 32
#define NREL 129
#define QRS  136          // qrel row stride (padded so mma tile 16 fits)

// ---------------- scratch (device globals: sanctioned workaround) ----------
__device__ __half g_xh[(size_t)BB * SQ * DD];    // X fp16, k pair-permuted
__device__ __half g_wth[3 * (size_t)DD * DD];    // W^T [n][k] fp16, k pair-permuted
__device__ __half g_qh[(size_t)BH * SQ * HD];    // [bh][s][d]  fp16, natural cols
__device__ __half g_kh[(size_t)BH * SQ * HD];    // [bh][s][d]  fp16, pair-permuted d
__device__ __half g_vth[(size_t)BH * HD * SQ];   // [bh][d][s]  fp16, pair-permuted s
__device__ float  g_qrel[(size_t)BH * SQ * QRS]; // [bh][q][129 (pad 136)] fp32

// ---------------- helpers --------------------------------------------------
__device__ __forceinline__ float ex2f(float x) {
    float r; asm("ex2.approx.f32 %0, %1;" : "=f"(r) : "f"(x));
    return r;
}
__device__ __forceinline__ uint32_t h2b(float lo, float hi) {
    __half2 h = __floats2half2_rn(lo, hi);
    return *(uint32_t*)&h;
}
__device__ __forceinline__ uint32_t s2u(const void* p) {
    uint32_t a;
    asm("{ .reg .u64 t; cvta.to.shared.u64 t, %1; cvt.u32.u64 %0, t; }" : "=r"(a) : "l"(p));
    return a;
}
#define CPA16(s, g) asm volatile("cp.async.cg.shared.global [%0], [%1], 16;" :: "r"(s), "l"(g))
#define CPA4(s, g)  asm volatile("cp.async.ca.shared.global [%0], [%1], 4;"  :: "r"(s), "l"(g))
#define CPCOMMIT()  asm volatile("cp.async.commit_group;" ::: "memory")
#define CPWAIT0()   asm volatile("cp.async.wait_group 0;" ::: "memory")

// pair-interleave permutation within 16-element blocks:
// pair j (j<4) -> slot 2j ; pair j (j>=4) -> slot 2(j-4)+1
__device__ __forceinline__ int sperm(int s) {
    int j = (s >> 1) & 7;
    return (s & ~15) + ((((j & 3) << 1) | (j >> 2)) << 1) + (s & 1);
}
__device__ __forceinline__ int pslot(int j) {   // pair j -> pair-slot
    return (j < 4) ? 2 * j : 2 * j - 7;
}
// fp16 k16 mma
__device__ __forceinline__ void mma16(float4& d,
                                      uint32_t a0, uint32_t a1, uint32_t a2, uint32_t a3,
                                      uint32_t b0, uint32_t b1) {
    asm("mma.sync.aligned.m16n8k16.row.col.f32.f16.f16.f32 "
        "{%0,%1,%2,%3},{%4,%5,%6,%7},{%8,%9},{%0,%1,%2,%3};"
        : "+f"(d.x), "+f"(d.y), "+f"(d.z), "+f"(d.w)
        : "r"(a0), "r"(a1), "r"(a2), "r"(a3), "r"(b0), "r"(b1));
}

// ===========================================================================
// Kernel 0a: X -> fp16, k pair-permuted per 16-block. One 16-block/thread.
// ===========================================================================
__global__ __launch_bounds__(256) void convert_x(const float* __restrict__ X)
{
    const int idx = blockIdx.x * 256 + threadIdx.x;      // 16-block index
    const float4* src = (const float4*)X + (size_t)idx * 4;
    __half* dst = g_xh + (size_t)idx * 16;
    float f[16];
    *(float4*)(f)      = src[0];
    *(float4*)(f + 4)  = src[1];
    *(float4*)(f + 8)  = src[2];
    *(float4*)(f + 12) = src[3];
    #pragma unroll
    for (int j = 0; j < 8; j++)
        *(__half2*)&dst[2 * pslot(j)] = __floats2half2_rn(f[2 * j], f[2 * j + 1]);
}

// ===========================================================================
// Kernel 0b: W[k][n] -> W^T[n][k] fp16, k pair-permuted. 32x32 smem transpose.
// ===========================================================================
__global__ __launch_bounds__(256) void convert_w(
    const float* __restrict__ Wq, const float* __restrict__ Wk,
    const float* __restrict__ Wv)
{
    __shared__ float tile[32][33];
    const float* W = (blockIdx.z == 0) ? Wq : (blockIdx.z == 1) ? Wk : Wv;
    __half* out = g_wth + (size_t)blockIdx.z * DD * DD;
    const int k0 = blockIdx.y * 32, n0 = blockIdx.x * 32;
    const int t = threadIdx.x;
    {
        const int r = t >> 3, c = (t & 7) * 4;
        float4 v = *(const float4*)&W[(size_t)(k0 + r) * DD + n0 + c];
        tile[r][c] = v.x; tile[r][c + 1] = v.y; tile[r][c + 2] = v.z; tile[r][c + 3] = v.w;
    }
    __syncthreads();
    if (t < 64) {
        const int n = t >> 1, blk = t & 1;
        __half* drow = out + (size_t)(n0 + n) * DD + k0 + blk * 16;
        #pragma unroll
        for (int j = 0; j < 8; j++)
            *(__half2*)&drow[2 * pslot(j)] =
                __floats2half2_rn(tile[blk * 16 + 2 * j][n], tile[blk * 16 + 2 * j + 1][n]);
    }
}

// ===========================================================================
// Kernel 1: fused QKV projection, fp16 m16n8k16, pre-converted inputs.
// (unchanged from R10/R11 — measured good)
// ===========================================================================
#define AST 48   // smem row stride (halves)

__global__ __launch_bounds__(256) void qkv_gemm(
    const float* __restrict__ bq, const float* __restrict__ bk,
    const float* __restrict__ bv)
{
    __shared__ __half As[2][128 * AST];
    __shared__ __half Bs[2][128 * AST];

    const float* bias = (blockIdx.z == 0) ? bq : (blockIdx.z == 1) ? bk : bv;
    const __half* Wt = g_wth + (size_t)blockIdx.z * DD * DD;

    const int tid = threadIdx.x;
    const int wid = tid >> 5, lane = tid & 31, lr = lane >> 2, lc = lane & 3;
    const int wm = wid >> 1, wn = wid & 1;
    const int m0 = blockIdx.y * 128, n0 = blockIdx.x * 128;

    const int row = tid >> 1, hb = tid & 1;
    const __half* xp = g_xh + (size_t)(m0 + row) * DD + hb * 16;
    const __half* wp = Wt   + (size_t)(n0 + row) * DD + hb * 16;

    float4 acc[2][8];
    #pragma unroll
    for (int mt = 0; mt < 2; mt++)
        #pragma unroll
        for (int nt = 0; nt < 8; nt++) acc[mt][nt] = make_float4(0.f, 0.f, 0.f, 0.f);

    uint4 xa0 = *(const uint4*)(xp);
    uint4 xa1 = *(const uint4*)(xp + 8);
    uint4 wa0 = *(const uint4*)(wp);
    uint4 wa1 = *(const uint4*)(wp + 8);

    *(uint4*)&As[0][row * AST + hb * 24]     = xa0;
    *(uint4*)&As[0][row * AST + hb * 24 + 8] = xa1;
    *(uint4*)&Bs[0][row * AST + hb * 24]     = wa0;
    *(uint4*)&Bs[0][row * AST + hb * 24 + 8] = wa1;
    __syncthreads();

    for (int k0 = 0; k0 < DD; k0 += 32) {
        const int cur = (k0 >> 5) & 1;
        const bool haveNext = (k0 + 32) < DD;
        if (haveNext) {
            xa0 = *(const uint4*)(xp + k0 + 32);
            xa1 = *(const uint4*)(xp + k0 + 40);
            wa0 = *(const uint4*)(wp + k0 + 32);
            wa1 = *(const uint4*)(wp + k0 + 40);
        }

        const __half* Ac = As[cur];
        const __half* Bc = Bs[cur];
        #pragma unroll
        for (int kc = 0; kc < 2; kc++) {
            uint2 ua[2], ub[2];
            #pragma unroll
            for (int mt = 0; mt < 2; mt++) {
                const int mb = wm * 32 + mt * 16;
                ua[mt] = *(const uint2*)&Ac[(mb + lr) * AST + kc * 24 + 4 * lc];
                ub[mt] = *(const uint2*)&Ac[(mb + lr + 8) * AST + kc * 24 + 4 * lc];
            }
            #pragma unroll
            for (int nt = 0; nt < 8; nt++) {
                const int nb = wn * 64 + nt * 8;
                const uint2 vb = *(const uint2*)&Bc[(nb + lr) * AST + kc * 24 + 4 * lc];
                mma16(acc[0][nt], ua[0].x, ub[0].x, ua[0].y, ub[0].y, vb.x, vb.y);
                mma16(acc[1][nt], ua[1].x, ub[1].x, ua[1].y, ub[1].y, vb.x, vb.y);
            }
        }

        if (haveNext) {
            __half* Ab = As[cur ^ 1];
            __half* Bb = Bs[cur ^ 1];
            *(uint4*)&Ab[row * AST + hb * 24]     = xa0;
            *(uint4*)&Ab[row * AST + hb * 24 + 8] = xa1;
            *(uint4*)&Bb[row * AST + hb * 24]     = wa0;
            *(uint4*)&Bb[row * AST + hb * 24 + 8] = wa1;
        }
        __syncthreads();
    }

    // ---- epilogue: add bias, fp16 scatter ----
    if (blockIdx.z == 0) {
        #pragma unroll
        for (int mt = 0; mt < 2; mt++) {
            const int mA = m0 + wm * 32 + mt * 16 + lr;
            const int mB = mA + 8;
            #pragma unroll
            for (int nt = 0; nt < 8; nt++) {
                const int n = n0 + wn * 64 + nt * 8 + 2 * lc;
                const float b0v = __ldg(&bias[n]), b1v = __ldg(&bias[n + 1]);
                const int hh = n >> 6, dd = n & 63;
                {
                    const int bidx = mA >> 11, s = mA & 2047;
                    *(__half2*)&g_qh[(((size_t)(bidx * NH + hh)) * SQ + s) * HD + dd] =
                        __floats2half2_rn(acc[mt][nt].x + b0v, acc[mt][nt].y + b1v);
                }
                {
                    const int bidx = mB >> 11, s = mB & 2047;
                    *(__half2*)&g_qh[(((size_t)(bidx * NH + hh)) * SQ + s) * HD + dd] =
                        __floats2half2_rn(acc[mt][nt].z + b0v, acc[mt][nt].w + b1v);
                }
            }
        }
    } else if (blockIdx.z == 1) {
        #pragma unroll
        for (int mt = 0; mt < 2; mt++) {
            const int mA = m0 + wm * 32 + mt * 16 + lr;
            const int mB = mA + 8;
            #pragma unroll
            for (int nt = 0; nt < 8; nt++) {
                const int n = n0 + wn * 64 + nt * 8 + 2 * lc;
                const float b0v = __ldg(&bias[n]), b1v = __ldg(&bias[n + 1]);
                const int hh = n >> 6, dd = n & 63;
                const int pc = sperm(dd);
                {
                    const int bidx = mA >> 11, s = mA & 2047;
                    *(__half2*)&g_kh[(((size_t)(bidx * NH + hh)) * SQ + s) * HD + pc] =
                        __floats2half2_rn(acc[mt][nt].x + b0v, acc[mt][nt].y + b1v);
                }
                {
                    const int bidx = mB >> 11, s = mB & 2047;
                    *(__half2*)&g_kh[(((size_t)(bidx * NH + hh)) * SQ + s) * HD + pc] =
                        __floats2half2_rn(acc[mt][nt].z + b0v, acc[mt][nt].w + b1v);
                }
            }
        }
    } else {
        #pragma unroll
        for (int mt = 0; mt < 2; mt++) {
            const int mA = m0 + wm * 32 + mt * 16 + lr;
            const int mB = mA + 8;
            const int bA = mA >> 11, sA = mA & 2047;
            const int bB = mB >> 11, sB = mB & 2047;
            const int pA = sperm(sA), pB = sperm(sB);
            #pragma unroll
            for (int nt = 0; nt < 8; nt++) {
                const int n = n0 + wn * 64 + nt * 8 + 2 * lc;
                const float b0v = __ldg(&bias[n]), b1v = __ldg(&bias[n + 1]);
                const int hh = n >> 6, dd = n & 63;
                const size_t base0 = ((size_t)(bA * NH + hh) * HD + dd) * SQ;
                const size_t base1 = ((size_t)(bB * NH + hh) * HD + dd) * SQ;
                g_vth[base0 + pA]      = __float2half_rn(acc[mt][nt].x + b0v);
                g_vth[base0 + SQ + pA] = __float2half_rn(acc[mt][nt].y + b1v);
                g_vth[base1 + pB]      = __float2half_rn(acc[mt][nt].z + b0v);
                g_vth[base1 + SQ + pB] = __float2half_rn(acc[mt][nt].w + b1v);
            }
        }
    }
}

// ===========================================================================
// Kernel 2: qrel via fp16 mma (unchanged from R11 — 22us measured)
// ===========================================================================
__global__ __launch_bounds__(256) void qrel_mma(const float* __restrict__ emb_k)
{
    __shared__ __half ekh[136 * 80];
    const int tid = threadIdx.x;
    const int wid = tid >> 5, lane = tid & 31, lr = lane >> 2, lc = lane & 3;
    const int bh = blockIdx.y, q0 = blockIdx.x * 128;
    const int r0w = wid * 16;
    const int rowA = r0w + lr, rowB = rowA + 8;

    for (int idx = tid; idx < 136 * 32; idx += 256) {
        const int r = idx >> 5, j = idx & 31;
        const int blk = j >> 3, jj = j & 7;
        float lo = 0.f, hi = 0.f;
        if (r < NREL) {
            lo = emb_k[r * HD + blk * 16 + 2 * jj];
            hi = emb_k[r * HD + blk * 16 + 2 * jj + 1];
        }
        *(__half2*)&ekh[r * 80 + blk * 16 + 2 * pslot(jj)] = __floats2half2_rn(lo, hi);
    }

    uint32_t qf[4][4];
    {
        const __half* qA = g_qh + ((size_t)bh * SQ + q0 + rowA) * HD;
        const __half* qB = qA + 8 * HD;
        #pragma unroll
        for (int kc = 0; kc < 4; kc++) {
            qf[kc][0] = *(const uint32_t*)&qA[kc * 16 + 2 * lc];
            qf[kc][1] = *(const uint32_t*)&qB[kc * 16 + 2 * lc];
            qf[kc][2] = *(const uint32_t*)&qA[kc * 16 + 2 * lc + 8];
            qf[kc][3] = *(const uint32_t*)&qB[kc * 16 + 2 * lc + 8];
        }
    }
    __syncthreads();

    float4 racc[17];
    #pragma unroll
    for (int nt = 0; nt < 17; nt++) racc[nt] = make_float4(0.f, 0.f, 0.f, 0.f);
    const uint2* E2 = (const uint2*)ekh;
    #pragma unroll
    for (int kc = 0; kc < 4; kc++) {
        #pragma unroll
        for (int nt = 0; nt < 17; nt++) {
            const uint2 eb = E2[(nt * 8 + lr) * 20 + kc * 4 + lc];
            mma16(racc[nt], qf[kc][0], qf[kc][1], qf[kc][2], qf[kc][3], eb.x, eb.y);
        }
    }

    float* orA = g_qrel + ((size_t)bh * SQ + q0 + rowA) * QRS;
    float* orB = g_qrel + ((size_t)bh * SQ + q0 + rowB) * QRS;
    #pragma unroll
    for (int nt = 0; nt < 17; nt++) {
        const int c0 = nt * 8 + 2 * lc;
        *(float2*)&orA[c0] = make_float2(racc[nt].x, racc[nt].y);
        *(float2*)&orB[c0] = make_float2(racc[nt].z, racc[nt].w);
    }
}

// ===========================================================================
// Kernel 3: flash attention, fp16 m16n8k16, R11 config + cp.async
// double-buffered K/V/mask tiles (zero register cost), one barrier/tile.
// smem: 2 x (Ks[64][80] + Vt[64][80]) = 40960B, pw fp32 [128][144] = 73728B,
// msk 2 x 64 f32 = 512B  => 115200B -> 2 CTAs/SM.
// ===========================================================================
#define PWS 144
#define KVST 20480                       // bytes per K+V stage
#define PW_OFF (2 * KVST)                // 40960
#define MSK_OFF (PW_OFF + 128 * PWS * 4) // 114688
#define ATTN_SMEM_BYTES (MSK_OFF + 512)
#define C1LOG2E 0.18033688011112042f    // 0.125 * log2(e)
#define LOG2E   1.4426950408889634f

__global__ __launch_bounds__(256, 2) void attn_f16(
    const float* __restrict__ mask,
    const float* __restrict__ emb_v,
    float* __restrict__ out)
{
    extern __shared__ char smc[];
    float* pw = (float*)(smc + PW_OFF);              // [128][144]

    const int tid = threadIdx.x;
    const int wid = tid >> 5, lane = tid & 31, lr = lane >> 2, lc = lane & 3;
    const int bh = blockIdx.y, b = bh >> 4, h = bh & 15;
    const int q0 = blockIdx.x * 128;
    const int r0w = wid * 16;
    const int rowA = r0w + lr, rowB = rowA + 8;
    const uint32_t smu = s2u(smc);

    for (int i = lane; i < 16 * PWS; i += 32) pw[r0w * PWS + i] = 0.f;

    uint32_t qf[4][4];
    {
        const __half* qA = g_qh + ((size_t)bh * SQ + q0 + rowA) * HD;
        const __half* qB = qA + 8 * HD;
        #pragma unroll
        for (int kc = 0; kc < 4; kc++) {
            qf[kc][0] = *(const uint32_t*)&qA[kc * 16 + 2 * lc];
            qf[kc][1] = *(const uint32_t*)&qB[kc * 16 + 2 * lc];
            qf[kc][2] = *(const uint32_t*)&qA[kc * 16 + 2 * lc + 8];
            qf[kc][3] = *(const uint32_t*)&qB[kc * 16 + 2 * lc + 8];
        }
    }
    const float* qrA = g_qrel + ((size_t)bh * SQ + q0 + rowA) * QRS;
    const float* qrB = g_qrel + ((size_t)bh * SQ + q0 + rowB) * QRS;
    const float rb0A = qrA[0], rb1A = qrA[128];
    const float rb0B = qrB[0], rb1B = qrB[128];

    float l_a = 0.f, l_b = 0.f;
    float h0A = 0.f, h1A = 0.f, h0B = 0.f, h1B = 0.f;
    float4 acc[8];
    #pragma unroll
    for (int nt = 0; nt < 8; nt++) acc[nt] = make_float4(0.f, 0.f, 0.f, 0.f);

    // loader geometry
    const int frow = tid >> 2, fcq = (tid & 3) * 16;
    const __half* kbase = g_kh  + ((size_t)bh * SQ + frow) * HD + fcq;   // +k0*HD
    const __half* vbase = g_vth + ((size_t)bh * HD + frow) * SQ + fcq;   // +k0
    const uint32_t sKV = smu + (uint32_t)(frow * 80 + fcq) * 2;          // +stage*KVST
    const float* mbase = mask + (size_t)b * SQ;

    // prologue: tile 0 -> stage 0
    {
        CPA16(sKV,          kbase);
        CPA16(sKV + 16,     kbase + 8);
        CPA16(sKV + 10240,      vbase);
        CPA16(sKV + 10240 + 16, vbase + 8);
        if (tid < 64) CPA4(smu + MSK_OFF + tid * 4, mbase + tid);
        CPCOMMIT();
        CPWAIT0();
    }
    __syncthreads();

    for (int t = 0; t < 32; t++) {
        const int k0 = t * 64;
        const int cur = t & 1;
        // issue next tile into alternate stage (no registers held)
        if (t + 1 < 32) {
            const uint32_t sN = sKV + (cur ^ 1) * KVST;
            const __half* kp = kbase + (size_t)(k0 + 64) * HD;
            const __half* vp = vbase + (k0 + 64);
            CPA16(sN,          kp);
            CPA16(sN + 16,     kp + 8);
            CPA16(sN + 10240,      vp);
            CPA16(sN + 10240 + 16, vp + 8);
            if (tid < 64) CPA4(smu + MSK_OFF + (cur ^ 1) * 256 + tid * 4,
                               mbase + k0 + 64 + tid);
            CPCOMMIT();
        }

        const __half* Ks = (const __half*)(smc + cur * KVST);
        const __half* Vt = (const __half*)(smc + cur * KVST + 10240);
        const float* mskc = (const float*)(smc + MSK_OFF + cur * 256);

        const int diff = q0 - k0;
        const bool nearT = (diff >= -128) && (diff <= 64);
        const int delta = diff + 64;

        float4 sc4[8];
        #pragma unroll
        for (int nt = 0; nt < 8; nt++) sc4[nt] = make_float4(0.f, 0.f, 0.f, 0.f);
        {
            const uint2* K2 = (const uint2*)Ks;
            #pragma unroll
            for (int kc = 0; kc < 4; kc++) {
                #pragma unroll
                for (int nt = 0; nt < 8; nt++) {
                    const uint2 kb = K2[(nt * 8 + lr) * 20 + kc * 4 + lc];
                    mma16(sc4[nt], qf[kc][0], qf[kc][1], qf[kc][2], qf[kc][3], kb.x, kb.y);
                }
            }
        }

        if (nearT) {
            #pragma unroll
            for (int nt = 0; nt < 8; nt++) {
                const int c0 = nt * 8 + 2 * lc;
                const float2 mk = *(const float2*)&mskc[c0];
                const float mkx = mk.x * LOG2E, mky = mk.y * LOG2E;
                const int bA = rowA + delta - c0;
                const int bB = rowB + delta - c0;
                const int bAx = min(max(bA, 0), 128),     bAy = min(max(bA - 1, 0), 128);
                const int bBx = min(max(bB, 0), 128),     bBy = min(max(bB - 1, 0), 128);
                sc4[nt].x = (sc4[nt].x + __ldg(&qrA[bAx])) * C1LOG2E + mkx;
                sc4[nt].y = (sc4[nt].y + __ldg(&qrA[bAy])) * C1LOG2E + mky;
                sc4[nt].z = (sc4[nt].z + __ldg(&qrB[bBx])) * C1LOG2E + mkx;
                sc4[nt].w = (sc4[nt].w + __ldg(&qrB[bBy])) * C1LOG2E + mky;
            }
        } else {
            const float rbA = (diff > 0) ? rb1A : rb0A;
            const float rbB = (diff > 0) ? rb1B : rb0B;
            #pragma unroll
            for (int nt = 0; nt < 8; nt++) {
                const int c0 = nt * 8 + 2 * lc;
                const float2 mk = *(const float2*)&mskc[c0];
                const float mkx = mk.x * LOG2E, mky = mk.y * LOG2E;
                sc4[nt].x = (sc4[nt].x + rbA) * C1LOG2E + mkx;
                sc4[nt].y = (sc4[nt].y + rbA) * C1LOG2E + mky;
                sc4[nt].z = (sc4[nt].z + rbB) * C1LOG2E + mkx;
                sc4[nt].w = (sc4[nt].w + rbB) * C1LOG2E + mky;
            }
        }

        float psA = 0.f, psB = 0.f;
        #pragma unroll
        for (int nt = 0; nt < 8; nt++) {
            sc4[nt].x = ex2f(sc4[nt].x); psA += sc4[nt].x;
            sc4[nt].y = ex2f(sc4[nt].y); psA += sc4[nt].y;
            sc4[nt].z = ex2f(sc4[nt].z); psB += sc4[nt].z;
            sc4[nt].w = ex2f(sc4[nt].w); psB += sc4[nt].w;
        }

        if (!nearT) {
            if (diff > 0) { h1A += psA; h1B += psB; }
            else          { h0A += psA; h0B += psB; }
        } else {
            #pragma unroll
            for (int nt = 0; nt < 8; nt++) {
                const int c0 = nt * 8 + 2 * lc;
                const int bA = rowA + delta - c0;
                const int bB = rowB + delta - c0;
                if (bA >= 128) h1A += sc4[nt].x; else if (bA <= 0) h0A += sc4[nt].x; else pw[rowA * PWS + bA] += sc4[nt].x;
                if (bA - 1 >= 128) h1A += sc4[nt].y; else if (bA - 1 <= 0) h0A += sc4[nt].y; else pw[rowA * PWS + bA - 1] += sc4[nt].y;
                if (bB >= 128) h1B += sc4[nt].z; else if (bB <= 0) h0B += sc4[nt].z; else pw[rowB * PWS + bB] += sc4[nt].z;
                if (bB - 1 >= 128) h1B += sc4[nt].w; else if (bB - 1 <= 0) h0B += sc4[nt].w; else pw[rowB * PWS + bB - 1] += sc4[nt].w;
            }
        }

        psA += __shfl_xor_sync(0xffffffffu, psA, 1);
        psA += __shfl_xor_sync(0xffffffffu, psA, 2);
        psB += __shfl_xor_sync(0xffffffffu, psB, 1);
        psB += __shfl_xor_sync(0xffffffffu, psB, 2);
        l_a += psA; l_b += psB;

        {
            const uint2* V2 = (const uint2*)Vt;
            #pragma unroll
            for (int kc = 0; kc < 4; kc++) {
                const uint32_t a0 = h2b(sc4[2 * kc].x,     sc4[2 * kc].y);
                const uint32_t a1 = h2b(sc4[2 * kc].z,     sc4[2 * kc].w);
                const uint32_t a2 = h2b(sc4[2 * kc + 1].x, sc4[2 * kc + 1].y);
                const uint32_t a3 = h2b(sc4[2 * kc + 1].z, sc4[2 * kc + 1].w);
                #pragma unroll
                for (int nt = 0; nt < 8; nt++) {
                    const uint2 vb = V2[(nt * 8 + lr) * 20 + kc * 4 + lc];
                    mma16(acc[nt], a0, a1, a2, a3, vb.x, vb.y);
                }
            }
        }

        CPWAIT0();        // next-tile fill complete (landed during compute)
        __syncthreads();  // single barrier per tile
    }

    h0A += __shfl_xor_sync(0xffffffffu, h0A, 1);
    h0A += __shfl_xor_sync(0xffffffffu, h0A, 2);
    h1A += __shfl_xor_sync(0xffffffffu, h1A, 1);
    h1A += __shfl_xor_sync(0xffffffffu, h1A, 2);
    h0B += __shfl_xor_sync(0xffffffffu, h0B, 1);
    h0B += __shfl_xor_sync(0xffffffffu, h0B, 2);
    h1B += __shfl_xor_sync(0xffffffffu, h1B, 1);
    h1B += __shfl_xor_sync(0xffffffffu, h1B, 2);
    if (lc == 0) {
        pw[rowA * PWS + 0]   += h0A;
        pw[rowA * PWS + 128] += h1A;
        pw[rowB * PWS + 0]   += h0B;
        pw[rowB * PWS + 128] += h1B;
    }
    __syncthreads();

    __half* evt = (__half*)smc;   // 64*144*2 = 18432B, fits in KV stages
    for (int idx = tid; idx < 64 * PWS; idx += 256) {
        const int d = idx / PWS, r = idx - d * PWS;
        evt[idx] = (r < NREL) ? __float2half_rn(emb_v[r * HD + d]) : __half(0.f);
    }
    __syncthreads();

    float4 racc[8];
    #pragma unroll
    for (int nt = 0; nt < 8; nt++) racc[nt] = make_float4(0.f, 0.f, 0.f, 0.f);
    #pragma unroll
    for (int kc = 0; kc < 9; kc++) {   // k = 144 = 9 * 16
        const int kb = kc * 16 + 2 * lc;
        const uint32_t a0 = h2b(pw[rowA * PWS + kb],     pw[rowA * PWS + kb + 1]);
        const uint32_t a1 = h2b(pw[rowB * PWS + kb],     pw[rowB * PWS + kb + 1]);
        const uint32_t a2 = h2b(pw[rowA * PWS + kb + 8], pw[rowA * PWS + kb + 9]);
        const uint32_t a3 = h2b(pw[rowB * PWS + kb + 8], pw[rowB * PWS + kb + 9]);
        #pragma unroll
        for (int nt = 0; nt < 8; nt++) {
            const uint32_t b0 = *(const uint32_t*)&evt[(nt * 8 + lr) * PWS + kb];
            const uint32_t b1 = *(const uint32_t*)&evt[(nt * 8 + lr) * PWS + kb + 8];
            mma16(racc[nt], a0, a1, a2, a3, b0, b1);
        }
    }

    const float rlA = 1.f / l_a, rlB = 1.f / l_b;
    float* opA = out + ((size_t)(b * SQ + q0 + rowA)) * DD + h * HD;
    float* opB = out + ((size_t)(b * SQ + q0 + rowB)) * DD + h * HD;
    #pragma unroll
    for (int nt = 0; nt < 8; nt++) {
        const int c0 = nt * 8 + 2 * lc;
        float2 oa;
        oa.x = (acc[nt].x + racc[nt].x) * rlA;
        oa.y = (acc[nt].y + racc[nt].y) * rlA;
        *(float2*)&opA[c0] = oa;
        float2 ob;
        ob.x = (acc[nt].z + racc[nt].z) * rlB;
        ob.y = (acc[nt].w + racc[nt].w) * rlB;
        *(float2*)&opB[c0] = ob;
    }
}

// ===========================================================================
extern "C" void kernel_launch(void* const* d_in, const int* in_sizes, int n_in,
                              void* d_out, int out_size)
{
    const float* hidden = (const float*)d_in[0];
    const float* mask   = (const float*)d_in[1];
    const float* Wq     = (const float*)d_in[2];
    const float* bq     = (const float*)d_in[3];
    const float* Wk     = (const float*)d_in[4];
    const float* bk     = (const float*)d_in[5];
    const float* Wv     = (const float*)d_in[6];
    const float* bv     = (const float*)d_in[7];
    const float* emb_k  = (const float*)d_in[8];
    const float* emb_v  = (const float*)d_in[9];
    float* out = (float*)d_out;

    convert_x<<<(BB * SQ * DD / 16) / 256, 256>>>(hidden);
    dim3 gw(DD / 32, DD / 32, 3);
    convert_w<<<gw, 256>>>(Wq, Wk, Wv);

    dim3 g1(DD / 128, (BB * SQ) / 128, 3);
    qkv_gemm<<<g1, 256>>>(bq, bk, bv);

    dim3 g2(SQ / 128, BH);
    qrel_mma<<<g2, 256>>>(emb_k);

    cudaFuncSetAttribute(attn_f16, cudaFuncAttributeMaxDynamicSharedMemorySize,
                         ATTN_SMEM_BYTES);
    dim3 g3(SQ / 128, BH);
    attn_f16<<<g3, 256, ATTN_SMEM_BYTES>>>(mask, emb_v, out);
}

// round 16
// speedup vs baseline: 1.6032x; 1.5158x over previous
#include <cuda_runtime.h>
#include <cuda_fp16.h>
#include <cstdint>

#define BB   2
#define SQ   2048
#define DD   1024
#define NH   16
#define HD   64
#define BH   (BB*NH)      // 32
#define NREL 129
#define QRS  136          // qrel row stride (padded so mma tile 16 fits)

// ---------------- scratch (device globals: sanctioned workaround) ----------
__device__ __half g_xh[(size_t)BB * SQ * DD];    // X fp16, k pair-permuted
__device__ __half g_wth[3 * (size_t)DD * DD];    // W^T [n][k] fp16, k pair-permuted
__device__ __half g_qh[(size_t)BH * SQ * HD];    // [bh][s][d]  fp16, natural cols
__device__ __half g_kh[(size_t)BH * SQ * HD];    // [bh][s][d]  fp16, pair-permuted d
__device__ __half g_vth[(size_t)BH * HD * SQ];   // [bh][d][s]  fp16, pair-permuted s
__device__ __half g_qrel[(size_t)BH * SQ * QRS]; // [bh][q][129 (pad 136)] fp16

// ---------------- helpers --------------------------------------------------
__device__ __forceinline__ float ex2f(float x) {
    float r; asm("ex2.approx.f32 %0, %1;" : "=f"(r) : "f"(x));
    return r;
}
__device__ __forceinline__ uint32_t h2b(float lo, float hi) {
    __half2 h = __floats2half2_rn(lo, hi);
    return *(uint32_t*)&h;
}
// pair-interleave permutation within 16-element blocks:
// pair j (j<4) -> slot 2j ; pair j (j>=4) -> slot 2(j-4)+1
__device__ __forceinline__ int sperm(int s) {
    int j = (s >> 1) & 7;
    return (s & ~15) + ((((j & 3) << 1) | (j >> 2)) << 1) + (s & 1);
}
__device__ __forceinline__ int pslot(int j) {   // pair j -> pair-slot
    return (j < 4) ? 2 * j : 2 * j - 7;
}
// fp16 k16 mma
__device__ __forceinline__ void mma16(float4& d,
                                      uint32_t a0, uint32_t a1, uint32_t a2, uint32_t a3,
                                      uint32_t b0, uint32_t b1) {
    asm("mma.sync.aligned.m16n8k16.row.col.f32.f16.f16.f32 "
        "{%0,%1,%2,%3},{%4,%5,%6,%7},{%8,%9},{%0,%1,%2,%3};"
        : "+f"(d.x), "+f"(d.y), "+f"(d.z), "+f"(d.w)
        : "r"(a0), "r"(a1), "r"(a2), "r"(a3), "r"(b0), "r"(b1));
}

// ===========================================================================
// Kernel 0a: X -> fp16, k pair-permuted per 16-block. One 16-block/thread.
// ===========================================================================
__global__ __launch_bounds__(256) void convert_x(const float* __restrict__ X)
{
    const int idx = blockIdx.x * 256 + threadIdx.x;      // 16-block index
    const float4* src = (const float4*)X + (size_t)idx * 4;
    __half* dst = g_xh + (size_t)idx * 16;
    float f[16];
    *(float4*)(f)      = src[0];
    *(float4*)(f + 4)  = src[1];
    *(float4*)(f + 8)  = src[2];
    *(float4*)(f + 12) = src[3];
    #pragma unroll
    for (int j = 0; j < 8; j++)
        *(__half2*)&dst[2 * pslot(j)] = __floats2half2_rn(f[2 * j], f[2 * j + 1]);
}

// ===========================================================================
// Kernel 0b: W[k][n] -> W^T[n][k] fp16, k pair-permuted. 32x32 smem transpose.
// ===========================================================================
__global__ __launch_bounds__(256) void convert_w(
    const float* __restrict__ Wq, const float* __restrict__ Wk,
    const float* __restrict__ Wv)
{
    __shared__ float tile[32][33];
    const float* W = (blockIdx.z == 0) ? Wq : (blockIdx.z == 1) ? Wk : Wv;
    __half* out = g_wth + (size_t)blockIdx.z * DD * DD;
    const int k0 = blockIdx.y * 32, n0 = blockIdx.x * 32;
    const int t = threadIdx.x;
    {
        const int r = t >> 3, c = (t & 7) * 4;
        float4 v = *(const float4*)&W[(size_t)(k0 + r) * DD + n0 + c];
        tile[r][c] = v.x; tile[r][c + 1] = v.y; tile[r][c + 2] = v.z; tile[r][c + 3] = v.w;
    }
    __syncthreads();
    if (t < 64) {
        const int n = t >> 1, blk = t & 1;
        __half* drow = out + (size_t)(n0 + n) * DD + k0 + blk * 16;
        #pragma unroll
        for (int j = 0; j < 8; j++)
            *(__half2*)&drow[2 * pslot(j)] =
                __floats2half2_rn(tile[blk * 16 + 2 * j][n], tile[blk * 16 + 2 * j + 1][n]);
    }
}

// ===========================================================================
// Kernel 1: fused QKV projection, fp16 m16n8k16, pre-converted inputs.
// (unchanged — measured good)
// ===========================================================================
#define AST 48   // smem row stride (halves)

__global__ __launch_bounds__(256) void qkv_gemm(
    const float* __restrict__ bq, const float* __restrict__ bk,
    const float* __restrict__ bv)
{
    __shared__ __half As[2][128 * AST];
    __shared__ __half Bs[2][128 * AST];

    const float* bias = (blockIdx.z == 0) ? bq : (blockIdx.z == 1) ? bk : bv;
    const __half* Wt = g_wth + (size_t)blockIdx.z * DD * DD;

    const int tid = threadIdx.x;
    const int wid = tid >> 5, lane = tid & 31, lr = lane >> 2, lc = lane & 3;
    const int wm = wid >> 1, wn = wid & 1;
    const int m0 = blockIdx.y * 128, n0 = blockIdx.x * 128;

    const int row = tid >> 1, hb = tid & 1;
    const __half* xp = g_xh + (size_t)(m0 + row) * DD + hb * 16;
    const __half* wp = Wt   + (size_t)(n0 + row) * DD + hb * 16;

    float4 acc[2][8];
    #pragma unroll
    for (int mt = 0; mt < 2; mt++)
        #pragma unroll
        for (int nt = 0; nt < 8; nt++) acc[mt][nt] = make_float4(0.f, 0.f, 0.f, 0.f);

    uint4 xa0 = *(const uint4*)(xp);
    uint4 xa1 = *(const uint4*)(xp + 8);
    uint4 wa0 = *(const uint4*)(wp);
    uint4 wa1 = *(const uint4*)(wp + 8);

    *(uint4*)&As[0][row * AST + hb * 24]     = xa0;
    *(uint4*)&As[0][row * AST + hb * 24 + 8] = xa1;
    *(uint4*)&Bs[0][row * AST + hb * 24]     = wa0;
    *(uint4*)&Bs[0][row * AST + hb * 24 + 8] = wa1;
    __syncthreads();

    for (int k0 = 0; k0 < DD; k0 += 32) {
        const int cur = (k0 >> 5) & 1;
        const bool haveNext = (k0 + 32) < DD;
        if (haveNext) {
            xa0 = *(const uint4*)(xp + k0 + 32);
            xa1 = *(const uint4*)(xp + k0 + 40);
            wa0 = *(const uint4*)(wp + k0 + 32);
            wa1 = *(const uint4*)(wp + k0 + 40);
        }

        const __half* Ac = As[cur];
        const __half* Bc = Bs[cur];
        #pragma unroll
        for (int kc = 0; kc < 2; kc++) {
            uint2 ua[2], ub[2];
            #pragma unroll
            for (int mt = 0; mt < 2; mt++) {
                const int mb = wm * 32 + mt * 16;
                ua[mt] = *(const uint2*)&Ac[(mb + lr) * AST + kc * 24 + 4 * lc];
                ub[mt] = *(const uint2*)&Ac[(mb + lr + 8) * AST + kc * 24 + 4 * lc];
            }
            #pragma unroll
            for (int nt = 0; nt < 8; nt++) {
                const int nb = wn * 64 + nt * 8;
                const uint2 vb = *(const uint2*)&Bc[(nb + lr) * AST + kc * 24 + 4 * lc];
                mma16(acc[0][nt], ua[0].x, ub[0].x, ua[0].y, ub[0].y, vb.x, vb.y);
                mma16(acc[1][nt], ua[1].x, ub[1].x, ua[1].y, ub[1].y, vb.x, vb.y);
            }
        }

        if (haveNext) {
            __half* Ab = As[cur ^ 1];
            __half* Bb = Bs[cur ^ 1];
            *(uint4*)&Ab[row * AST + hb * 24]     = xa0;
            *(uint4*)&Ab[row * AST + hb * 24 + 8] = xa1;
            *(uint4*)&Bb[row * AST + hb * 24]     = wa0;
            *(uint4*)&Bb[row * AST + hb * 24 + 8] = wa1;
        }
        __syncthreads();
    }

    // ---- epilogue: add bias, fp16 scatter ----
    if (blockIdx.z == 0) {
        #pragma unroll
        for (int mt = 0; mt < 2; mt++) {
            const int mA = m0 + wm * 32 + mt * 16 + lr;
            const int mB = mA + 8;
            #pragma unroll
            for (int nt = 0; nt < 8; nt++) {
                const int n = n0 + wn * 64 + nt * 8 + 2 * lc;
                const float b0v = __ldg(&bias[n]), b1v = __ldg(&bias[n + 1]);
                const int hh = n >> 6, dd = n & 63;
                {
                    const int bidx = mA >> 11, s = mA & 2047;
                    *(__half2*)&g_qh[(((size_t)(bidx * NH + hh)) * SQ + s) * HD + dd] =
                        __floats2half2_rn(acc[mt][nt].x + b0v, acc[mt][nt].y + b1v);
                }
                {
                    const int bidx = mB >> 11, s = mB & 2047;
                    *(__half2*)&g_qh[(((size_t)(bidx * NH + hh)) * SQ + s) * HD + dd] =
                        __floats2half2_rn(acc[mt][nt].z + b0v, acc[mt][nt].w + b1v);
                }
            }
        }
    } else if (blockIdx.z == 1) {
        #pragma unroll
        for (int mt = 0; mt < 2; mt++) {
            const int mA = m0 + wm * 32 + mt * 16 + lr;
            const int mB = mA + 8;
            #pragma unroll
            for (int nt = 0; nt < 8; nt++) {
                const int n = n0 + wn * 64 + nt * 8 + 2 * lc;
                const float b0v = __ldg(&bias[n]), b1v = __ldg(&bias[n + 1]);
                const int hh = n >> 6, dd = n & 63;
                const int pc = sperm(dd);
                {
                    const int bidx = mA >> 11, s = mA & 2047;
                    *(__half2*)&g_kh[(((size_t)(bidx * NH + hh)) * SQ + s) * HD + pc] =
                        __floats2half2_rn(acc[mt][nt].x + b0v, acc[mt][nt].y + b1v);
                }
                {
                    const int bidx = mB >> 11, s = mB & 2047;
                    *(__half2*)&g_kh[(((size_t)(bidx * NH + hh)) * SQ + s) * HD + pc] =
                        __floats2half2_rn(acc[mt][nt].z + b0v, acc[mt][nt].w + b1v);
                }
            }
        }
    } else {
        #pragma unroll
        for (int mt = 0; mt < 2; mt++) {
            const int mA = m0 + wm * 32 + mt * 16 + lr;
            const int mB = mA + 8;
            const int bA = mA >> 11, sA = mA & 2047;
            const int bB = mB >> 11, sB = mB & 2047;
            const int pA = sperm(sA), pB = sperm(sB);
            #pragma unroll
            for (int nt = 0; nt < 8; nt++) {
                const int n = n0 + wn * 64 + nt * 8 + 2 * lc;
                const float b0v = __ldg(&bias[n]), b1v = __ldg(&bias[n + 1]);
                const int hh = n >> 6, dd = n & 63;
                const size_t base0 = ((size_t)(bA * NH + hh) * HD + dd) * SQ;
                const size_t base1 = ((size_t)(bB * NH + hh) * HD + dd) * SQ;
                g_vth[base0 + pA]      = __float2half_rn(acc[mt][nt].x + b0v);
                g_vth[base0 + SQ + pA] = __float2half_rn(acc[mt][nt].y + b1v);
                g_vth[base1 + pB]      = __float2half_rn(acc[mt][nt].z + b0v);
                g_vth[base1 + SQ + pB] = __float2half_rn(acc[mt][nt].w + b1v);
            }
        }
    }
}

// ===========================================================================
// Kernel 2: qrel via fp16 mma; OUTPUT NOW fp16 (halves write + reread traffic)
// ===========================================================================
__global__ __launch_bounds__(256) void qrel_mma(const float* __restrict__ emb_k)
{
    __shared__ __half ekh[136 * 80];
    const int tid = threadIdx.x;
    const int wid = tid >> 5, lane = tid & 31, lr = lane >> 2, lc = lane & 3;
    const int bh = blockIdx.y, q0 = blockIdx.x * 128;
    const int r0w = wid * 16;
    const int rowA = r0w + lr, rowB = rowA + 8;

    for (int idx = tid; idx < 136 * 32; idx += 256) {
        const int r = idx >> 5, j = idx & 31;
        const int blk = j >> 3, jj = j & 7;
        float lo = 0.f, hi = 0.f;
        if (r < NREL) {
            lo = emb_k[r * HD + blk * 16 + 2 * jj];
            hi = emb_k[r * HD + blk * 16 + 2 * jj + 1];
        }
        *(__half2*)&ekh[r * 80 + blk * 16 + 2 * pslot(jj)] = __floats2half2_rn(lo, hi);
    }

    uint32_t qf[4][4];
    {
        const __half* qA = g_qh + ((size_t)bh * SQ + q0 + rowA) * HD;
        const __half* qB = qA + 8 * HD;
        #pragma unroll
        for (int kc = 0; kc < 4; kc++) {
            qf[kc][0] = *(const uint32_t*)&qA[kc * 16 + 2 * lc];
            qf[kc][1] = *(const uint32_t*)&qB[kc * 16 + 2 * lc];
            qf[kc][2] = *(const uint32_t*)&qA[kc * 16 + 2 * lc + 8];
            qf[kc][3] = *(const uint32_t*)&qB[kc * 16 + 2 * lc + 8];
        }
    }
    __syncthreads();

    float4 racc[17];
    #pragma unroll
    for (int nt = 0; nt < 17; nt++) racc[nt] = make_float4(0.f, 0.f, 0.f, 0.f);
    const uint2* E2 = (const uint2*)ekh;
    #pragma unroll
    for (int kc = 0; kc < 4; kc++) {
        #pragma unroll
        for (int nt = 0; nt < 17; nt++) {
            const uint2 eb = E2[(nt * 8 + lr) * 20 + kc * 4 + lc];
            mma16(racc[nt], qf[kc][0], qf[kc][1], qf[kc][2], qf[kc][3], eb.x, eb.y);
        }
    }

    __half* orA = g_qrel + ((size_t)bh * SQ + q0 + rowA) * QRS;
    __half* orB = g_qrel + ((size_t)bh * SQ + q0 + rowB) * QRS;
    #pragma unroll
    for (int nt = 0; nt < 17; nt++) {
        const int c0 = nt * 8 + 2 * lc;
        *(__half2*)&orA[c0] = __floats2half2_rn(racc[nt].x, racc[nt].y);
        *(__half2*)&orB[c0] = __floats2half2_rn(racc[nt].z, racc[nt].w);
    }
}

// ===========================================================================
// Kernel 3: flash attention, fp16 m16n8k16 — EXACT R11 (374us) config;
// only change: qrel bias reads are fp16.
// ===========================================================================
#define PWS 144
#define ATTN_SMEM_BYTES (10240 + 10240 + 128 * PWS * 4 + 256)
#define C1LOG2E 0.18033688011112042f    // 0.125 * log2(e)
#define LOG2E   1.4426950408889634f

__global__ __launch_bounds__(256, 2) void attn_f16(
    const float* __restrict__ mask,
    const float* __restrict__ emb_v,
    float* __restrict__ out)
{
    extern __shared__ char smc[];
    __half* Ks = (__half*)smc;                       // [64][80]
    __half* Vt = (__half*)(smc + 10240);             // [64(d)][80(s)]
    float*  pw = (float*)(smc + 20480);              // [128][144]
    float* msk = (float*)(smc + 20480 + 128 * PWS * 4);

    const int tid = threadIdx.x;
    const int wid = tid >> 5, lane = tid & 31, lr = lane >> 2, lc = lane & 3;
    const int bh = blockIdx.y, b = bh >> 4, h = bh & 15;
    const int q0 = blockIdx.x * 128;
    const int r0w = wid * 16;
    const int rowA = r0w + lr, rowB = rowA + 8;

    for (int i = lane; i < 16 * PWS; i += 32) pw[r0w * PWS + i] = 0.f;

    uint32_t qf[4][4];
    {
        const __half* qA = g_qh + ((size_t)bh * SQ + q0 + rowA) * HD;
        const __half* qB = qA + 8 * HD;
        #pragma unroll
        for (int kc = 0; kc < 4; kc++) {
            qf[kc][0] = *(const uint32_t*)&qA[kc * 16 + 2 * lc];
            qf[kc][1] = *(const uint32_t*)&qB[kc * 16 + 2 * lc];
            qf[kc][2] = *(const uint32_t*)&qA[kc * 16 + 2 * lc + 8];
            qf[kc][3] = *(const uint32_t*)&qB[kc * 16 + 2 * lc + 8];
        }
    }
    const __half* qrA = g_qrel + ((size_t)bh * SQ + q0 + rowA) * QRS;
    const __half* qrB = g_qrel + ((size_t)bh * SQ + q0 + rowB) * QRS;
    const float rb0A = __half2float(qrA[0]), rb1A = __half2float(qrA[128]);
    const float rb0B = __half2float(qrB[0]), rb1B = __half2float(qrB[128]);

    float l_a = 0.f, l_b = 0.f;
    float h0A = 0.f, h1A = 0.f, h0B = 0.f, h1B = 0.f;
    float4 acc[8];
    #pragma unroll
    for (int nt = 0; nt < 8; nt++) acc[nt] = make_float4(0.f, 0.f, 0.f, 0.f);

    for (int k0 = 0; k0 < SQ; k0 += 64) {
        __syncthreads();
        {
            const int row = tid >> 2, cq = (tid & 3) * 16;
            const __half* kp = g_kh  + ((size_t)bh * SQ + k0 + row) * HD + cq;
            const __half* vp = g_vth + ((size_t)bh * HD + row) * SQ + k0 + cq;
            *(uint4*)&Ks[row * 80 + cq]     = *(const uint4*)kp;
            *(uint4*)&Ks[row * 80 + cq + 8] = *(const uint4*)(kp + 8);
            *(uint4*)&Vt[row * 80 + cq]     = *(const uint4*)vp;
            *(uint4*)&Vt[row * 80 + cq + 8] = *(const uint4*)(vp + 8);
        }
        if (tid < 64) msk[tid] = mask[(size_t)b * SQ + k0 + tid] * LOG2E;
        __syncthreads();

        const int diff = q0 - k0;
        const bool nearT = (diff >= -128) && (diff <= 64);
        const int delta = diff + 64;

        float4 sc4[8];
        #pragma unroll
        for (int nt = 0; nt < 8; nt++) sc4[nt] = make_float4(0.f, 0.f, 0.f, 0.f);
        {
            const uint2* K2 = (const uint2*)Ks;
            #pragma unroll
            for (int kc = 0; kc < 4; kc++) {
                #pragma unroll
                for (int nt = 0; nt < 8; nt++) {
                    const uint2 kb = K2[(nt * 8 + lr) * 20 + kc * 4 + lc];
                    mma16(sc4[nt], qf[kc][0], qf[kc][1], qf[kc][2], qf[kc][3], kb.x, kb.y);
                }
            }
        }

        if (nearT) {
            #pragma unroll
            for (int nt = 0; nt < 8; nt++) {
                const int c0 = nt * 8 + 2 * lc;
                const float2 mk = *(const float2*)&msk[c0];
                const int bA = rowA + delta - c0;
                const int bB = rowB + delta - c0;
                const int bAx = min(max(bA, 0), 128),     bAy = min(max(bA - 1, 0), 128);
                const int bBx = min(max(bB, 0), 128),     bBy = min(max(bB - 1, 0), 128);
                sc4[nt].x = (sc4[nt].x + __half2float(qrA[bAx])) * C1LOG2E + mk.x;
                sc4[nt].y = (sc4[nt].y + __half2float(qrA[bAy])) * C1LOG2E + mk.y;
                sc4[nt].z = (sc4[nt].z + __half2float(qrB[bBx])) * C1LOG2E + mk.x;
                sc4[nt].w = (sc4[nt].w + __half2float(qrB[bBy])) * C1LOG2E + mk.y;
            }
        } else {
            const float rbA = (diff > 0) ? rb1A : rb0A;
            const float rbB = (diff > 0) ? rb1B : rb0B;
            #pragma unroll
            for (int nt = 0; nt < 8; nt++) {
                const int c0 = nt * 8 + 2 * lc;
                const float2 mk = *(const float2*)&msk[c0];
                sc4[nt].x = (sc4[nt].x + rbA) * C1LOG2E + mk.x;
                sc4[nt].y = (sc4[nt].y + rbA) * C1LOG2E + mk.y;
                sc4[nt].z = (sc4[nt].z + rbB) * C1LOG2E + mk.x;
                sc4[nt].w = (sc4[nt].w + rbB) * C1LOG2E + mk.y;
            }
        }

        float psA = 0.f, psB = 0.f;
        #pragma unroll
        for (int nt = 0; nt < 8; nt++) {
            sc4[nt].x = ex2f(sc4[nt].x); psA += sc4[nt].x;
            sc4[nt].y = ex2f(sc4[nt].y); psA += sc4[nt].y;
            sc4[nt].z = ex2f(sc4[nt].z); psB += sc4[nt].z;
            sc4[nt].w = ex2f(sc4[nt].w); psB += sc4[nt].w;
        }

        if (!nearT) {
            if (diff > 0) { h1A += psA; h1B += psB; }
            else          { h0A += psA; h0B += psB; }
        } else {
            #pragma unroll
            for (int nt = 0; nt < 8; nt++) {
                const int c0 = nt * 8 + 2 * lc;
                const int bA = rowA + delta - c0;
                const int bB = rowB + delta - c0;
                if (bA >= 128) h1A += sc4[nt].x; else if (bA <= 0) h0A += sc4[nt].x; else pw[rowA * PWS + bA] += sc4[nt].x;
                if (bA - 1 >= 128) h1A += sc4[nt].y; else if (bA - 1 <= 0) h0A += sc4[nt].y; else pw[rowA * PWS + bA - 1] += sc4[nt].y;
                if (bB >= 128) h1B += sc4[nt].z; else if (bB <= 0) h0B += sc4[nt].z; else pw[rowB * PWS + bB] += sc4[nt].z;
                if (bB - 1 >= 128) h1B += sc4[nt].w; else if (bB - 1 <= 0) h0B += sc4[nt].w; else pw[rowB * PWS + bB - 1] += sc4[nt].w;
            }
        }

        psA += __shfl_xor_sync(0xffffffffu, psA, 1);
        psA += __shfl_xor_sync(0xffffffffu, psA, 2);
        psB += __shfl_xor_sync(0xffffffffu, psB, 1);
        psB += __shfl_xor_sync(0xffffffffu, psB, 2);
        l_a += psA; l_b += psB;

        {
            const uint2* V2 = (const uint2*)Vt;
            #pragma unroll
            for (int kc = 0; kc < 4; kc++) {
                const uint32_t a0 = h2b(sc4[2 * kc].x,     sc4[2 * kc].y);
                const uint32_t a1 = h2b(sc4[2 * kc].z,     sc4[2 * kc].w);
                const uint32_t a2 = h2b(sc4[2 * kc + 1].x, sc4[2 * kc + 1].y);
                const uint32_t a3 = h2b(sc4[2 * kc + 1].z, sc4[2 * kc + 1].w);
                #pragma unroll
                for (int nt = 0; nt < 8; nt++) {
                    const uint2 vb = V2[(nt * 8 + lr) * 20 + kc * 4 + lc];
                    mma16(acc[nt], a0, a1, a2, a3, vb.x, vb.y);
                }
            }
        }
    }

    h0A += __shfl_xor_sync(0xffffffffu, h0A, 1);
    h0A += __shfl_xor_sync(0xffffffffu, h0A, 2);
    h1A += __shfl_xor_sync(0xffffffffu, h1A, 1);
    h1A += __shfl_xor_sync(0xffffffffu, h1A, 2);
    h0B += __shfl_xor_sync(0xffffffffu, h0B, 1);
    h0B += __shfl_xor_sync(0xffffffffu, h0B, 2);
    h1B += __shfl_xor_sync(0xffffffffu, h1B, 1);
    h1B += __shfl_xor_sync(0xffffffffu, h1B, 2);
    if (lc == 0) {
        pw[rowA * PWS + 0]   += h0A;
        pw[rowA * PWS + 128] += h1A;
        pw[rowB * PWS + 0]   += h0B;
        pw[rowB * PWS + 128] += h1B;
    }
    __syncthreads();

    __half* evt = (__half*)smc;   // 64*144*2 = 18432B <= 20480B
    for (int idx = tid; idx < 64 * PWS; idx += 256) {
        const int d = idx / PWS, r = idx - d * PWS;
        evt[idx] = (r < NREL) ? __float2half_rn(emb_v[r * HD + d]) : __half(0.f);
    }
    __syncthreads();

    float4 racc[8];
    #pragma unroll
    for (int nt = 0; nt < 8; nt++) racc[nt] = make_float4(0.f, 0.f, 0.f, 0.f);
    #pragma unroll
    for (int kc = 0; kc < 9; kc++) {   // k = 144 = 9 * 16
        const int kb = kc * 16 + 2 * lc;
        const uint32_t a0 = h2b(pw[rowA * PWS + kb],     pw[rowA * PWS + kb + 1]);
        const uint32_t a1 = h2b(pw[rowB * PWS + kb],     pw[rowB * PWS + kb + 1]);
        const uint32_t a2 = h2b(pw[rowA * PWS + kb + 8], pw[rowA * PWS + kb + 9]);
        const uint32_t a3 = h2b(pw[rowB * PWS + kb + 8], pw[rowB * PWS + kb + 9]);
        #pragma unroll
        for (int nt = 0; nt < 8; nt++) {
            const uint32_t b0 = *(const uint32_t*)&evt[(nt * 8 + lr) * PWS + kb];
            const uint32_t b1 = *(const uint32_t*)&evt[(nt * 8 + lr) * PWS + kb + 8];
            mma16(racc[nt], a0, a1, a2, a3, b0, b1);
        }
    }

    const float rlA = 1.f / l_a, rlB = 1.f / l_b;
    float* opA = out + ((size_t)(b * SQ + q0 + rowA)) * DD + h * HD;
    float* opB = out + ((size_t)(b * SQ + q0 + rowB)) * DD + h * HD;
    #pragma unroll
    for (int nt = 0; nt < 8; nt++) {
        const int c0 = nt * 8 + 2 * lc;
        float2 oa;
        oa.x = (acc[nt].x + racc[nt].x) * rlA;
        oa.y = (acc[nt].y + racc[nt].y) * rlA;
        *(float2*)&opA[c0] = oa;
        float2 ob;
        ob.x = (acc[nt].z + racc[nt].z) * rlB;
        ob.y = (acc[nt].w + racc[nt].w) * rlB;
        *(float2*)&opB[c0] = ob;
    }
}

// ===========================================================================
extern "C" void kernel_launch(void* const* d_in, const int* in_sizes, int n_in,
                              void* d_out, int out_size)
{
    const float* hidden = (const float*)d_in[0];
    const float* mask   = (const float*)d_in[1];
    const float* Wq     = (const float*)d_in[2];
    const float* bq     = (const float*)d_in[3];
    const float* Wk     = (const float*)d_in[4];
    const float* bk     = (const float*)d_in[5];
    const float* Wv     = (const float*)d_in[6];
    const float* bv     = (const float*)d_in[7];
    const float* emb_k  = (const float*)d_in[8];
    const float* emb_v  = (const float*)d_in[9];
    float* out = (float*)d_out;

    convert_x<<<(BB * SQ * DD / 16) / 256, 256>>>(hidden);
    dim3 gw(DD / 32, DD / 32, 3);
    convert_w<<<gw, 256>>>(Wq, Wk, Wv);

    dim3 g1(DD / 128, (BB * SQ) / 128, 3);
    qkv_gemm<<<g1, 256>>>(bq, bk, bv);

    dim3 g2(SQ / 128, BH);
    qrel_mma<<<g2, 256>>>(emb_k);

    cudaFuncSetAttribute(attn_f16, cudaFuncAttributeMaxDynamicSharedMemorySize,
                         ATTN_SMEM_BYTES);
    dim3 g3(SQ / 128, BH);
    attn_f16<<<g3, 256, ATTN_SMEM_BYTES>>>(mask, emb_v, out);
}